// round 8
// baseline (speedup 1.0000x reference)
#include <cuda_runtime.h>
#include <cuda_bf16.h>
#include <cstdint>

// Problem constants (fixed by the reference)
#define N_TOK 16384      // B*S = 8*2048
#define D_DIM 4096
#define D_VEC 1024       // D/4 float4 per row
#define N_EXP 8
#define CAP   2048       // capacity = B*S/E
#define WL_MAX 4096      // marginal-token worklist capacity

// Scratch (no device allocs allowed) ---------------------------------------
__device__ int g_routes[N_TOK];
__device__ int g_inv[N_TOK];     // inv[e*CAP + p] = source token or -1
__device__ int g_wl[WL_MAX];     // tokens with top-2 margin < threshold
__device__ int g_wl_cnt;

// ---------------------------------------------------------------------------
// Pass 0: reset worklist counter (graph-replayed every call)
// ---------------------------------------------------------------------------
__global__ void zero_kernel() { g_wl_cnt = 0; }

// ---------------------------------------------------------------------------
// Pass 1: routing (exact fp32). Each warp computes logits for 4 tokens so the
// W read (8 experts x 16KB, L2-resident) is amortized 4x; x rows stream once
// from HBM. Tokens whose top-2 margin is tiny are appended to a worklist for
// exact fp64 re-ranking (removes all my-side argmax noise).
// ---------------------------------------------------------------------------
__global__ void __launch_bounds__(256) route_kernel(
    const float4* __restrict__ x,   // [N_TOK][1024]
    const float4* __restrict__ W,   // [8][1024]
    const float*  __restrict__ b,   // [8]
    int* __restrict__ routes)
{
    const int warp = threadIdx.x >> 5;
    const int lane = threadIdx.x & 31;
    const int tbase = (blockIdx.x * 8 + warp) * 4;   // first of 4 tokens

    const float4* x0 = x + (size_t)tbase * D_VEC;

    float acc[4][N_EXP];
#pragma unroll
    for (int t = 0; t < 4; t++)
#pragma unroll
        for (int e = 0; e < N_EXP; e++) acc[t][e] = 0.f;

#pragma unroll 4
    for (int i = 0; i < 32; i++) {
        const int idx = i * 32 + lane;
        float4 xv0 = __ldg(x0 + idx);
        float4 xv1 = __ldg(x0 + D_VEC + idx);
        float4 xv2 = __ldg(x0 + 2 * D_VEC + idx);
        float4 xv3 = __ldg(x0 + 3 * D_VEC + idx);
#pragma unroll
        for (int e = 0; e < N_EXP; e++) {
            float4 wv = __ldg(W + e * D_VEC + idx);
            acc[0][e] += xv0.x * wv.x + xv0.y * wv.y + xv0.z * wv.z + xv0.w * wv.w;
            acc[1][e] += xv1.x * wv.x + xv1.y * wv.y + xv1.z * wv.z + xv1.w * wv.w;
            acc[2][e] += xv2.x * wv.x + xv2.y * wv.y + xv2.z * wv.z + xv2.w * wv.w;
            acc[3][e] += xv3.x * wv.x + xv3.y * wv.y + xv3.z * wv.z + xv3.w * wv.w;
        }
    }

    // Butterfly reduce across the warp
#pragma unroll
    for (int t = 0; t < 4; t++) {
#pragma unroll
        for (int e = 0; e < N_EXP; e++) {
            float v = acc[t][e];
#pragma unroll
            for (int off = 16; off > 0; off >>= 1)
                v += __shfl_xor_sync(0xFFFFFFFFu, v, off);
            acc[t][e] = v;
        }
    }

    if (lane == 0) {
#pragma unroll
        for (int t = 0; t < 4; t++) {
            float best = -1e30f, second = -1e30f;
            int bi = 0;
#pragma unroll
            for (int e = 0; e < N_EXP; e++) {
                float l = acc[t][e] + b[e];
                if (l > best) { second = best; best = l; bi = e; }
                else if (l > second) { second = l; }
            }
            routes[tbase + t] = bi;
            if (best - second < 1e-2f) {       // marginal: exact re-rank later
                int slot = atomicAdd(&g_wl_cnt, 1);
                if (slot < WL_MAX) g_wl[slot] = tbase + t;
            }
        }
    }
}

// ---------------------------------------------------------------------------
// Pass 1b: fp64 refinement of marginal tokens (expected ~20 tokens).
// One block per worklist entry (strided); exact double-precision 8-way dot.
// ---------------------------------------------------------------------------
__global__ void __launch_bounds__(256) refine_kernel(
    const float* __restrict__ x,
    const float* __restrict__ W,
    const float* __restrict__ b,
    int* __restrict__ routes)
{
    __shared__ double sred[8][N_EXP];   // [warp][expert]
    const int tid  = threadIdx.x;
    const int warp = tid >> 5;
    const int lane = tid & 31;

    int cnt = g_wl_cnt;
    if (cnt > WL_MAX) cnt = WL_MAX;

    for (int w = blockIdx.x; w < cnt; w += gridDim.x) {
        const int tok = g_wl[w];
        const float* xr = x + (size_t)tok * D_DIM;

        double p[N_EXP];
#pragma unroll
        for (int e = 0; e < N_EXP; e++) p[e] = 0.0;

        for (int d = tid; d < D_DIM; d += 256) {
            const double xv = (double)__ldg(xr + d);
#pragma unroll
            for (int e = 0; e < N_EXP; e++)
                p[e] += xv * (double)__ldg(W + e * D_DIM + d);
        }

#pragma unroll
        for (int e = 0; e < N_EXP; e++) {
            double v = p[e];
#pragma unroll
            for (int off = 16; off > 0; off >>= 1)
                v += __shfl_xor_sync(0xFFFFFFFFu, v, off);
            if (lane == 0) sred[warp][e] = v;
        }
        __syncthreads();

        if (tid == 0) {
            double best = -1e300; int bi = 0;
#pragma unroll
            for (int e = 0; e < N_EXP; e++) {
                double s = (double)b[e];
#pragma unroll
                for (int wi = 0; wi < 8; wi++) s += sred[wi][e];
                if (s > best) { best = s; bi = e; }   // strict > : first-max
            }
            routes[tok] = bi;
        }
        __syncthreads();
    }
}

// ---------------------------------------------------------------------------
// Pass 2: single-CTA stable scan over token order. Each of 256 threads owns a
// contiguous chunk of 64 tokens; per-expert chunk counts are exclusively
// scanned in smem; then each thread assigns positions and fills g_inv.
// ---------------------------------------------------------------------------
__global__ void __launch_bounds__(256) scan_kernel(
    const int* __restrict__ routes, int* __restrict__ inv)
{
    __shared__ int cnt[256][N_EXP];   // 8 KB
    const int t = threadIdx.x;

    int c[N_EXP];
#pragma unroll
    for (int e = 0; e < N_EXP; e++) c[e] = 0;

    const int base = t * 64;
#pragma unroll 4
    for (int k = 0; k < 64; k++) c[routes[base + k]]++;

#pragma unroll
    for (int e = 0; e < N_EXP; e++) cnt[t][e] = c[e];
    __syncthreads();

    if (t < N_EXP) {
        int running = 0;
        for (int j = 0; j < 256; j++) {
            int v = cnt[j][t];
            cnt[j][t] = running;
            running += v;
        }
    }
    __syncthreads();

    for (int i = t; i < N_TOK; i += 256) inv[i] = -1;
    __syncthreads();

    int off[N_EXP];
#pragma unroll
    for (int e = 0; e < N_EXP; e++) off[e] = cnt[t][e];

    for (int k = 0; k < 64; k++) {
        const int tok = base + k;
        const int r = routes[tok];
        const int p = off[r]++;
        if (p < CAP) inv[r * CAP + p] = tok;
    }
}

// ---------------------------------------------------------------------------
// Pass 3: gather. One CTA per output row: copy x[inv[row]] or write zeros.
// ---------------------------------------------------------------------------
__global__ void __launch_bounds__(256) gather_kernel(
    const float4* __restrict__ x,
    const int*   __restrict__ inv,
    float4* __restrict__ out)
{
    const int row = blockIdx.x;
    const int src = __ldg(inv + row);         // uniform broadcast
    float4* o = out + (size_t)row * D_VEC;
    const int t = threadIdx.x;

    if (src >= 0) {
        const float4* s = x + (size_t)src * D_VEC;
#pragma unroll
        for (int i = 0; i < 4; i++)
            o[t + 256 * i] = __ldg(s + t + 256 * i);
    } else {
        const float4 z = make_float4(0.f, 0.f, 0.f, 0.f);
#pragma unroll
        for (int i = 0; i < 4; i++)
            o[t + 256 * i] = z;
    }
}

// ---------------------------------------------------------------------------
extern "C" void kernel_launch(void* const* d_in, const int* in_sizes, int n_in,
                              void* d_out, int out_size)
{
    const float* x = (const float*)d_in[0];   // [8,2048,4096]
    const float* W = (const float*)d_in[1];   // [8,4096]
    const float* b = (const float*)d_in[2];   // [8]
    float* out = (float*)d_out;               // [16384,4096]

    int* routes; cudaGetSymbolAddress((void**)&routes, g_routes);
    int* inv;    cudaGetSymbolAddress((void**)&inv,    g_inv);

    zero_kernel<<<1, 1>>>();
    route_kernel<<<N_TOK / 32, 256>>>(
        (const float4*)x, (const float4*)W, b, routes);
    refine_kernel<<<64, 256>>>(x, W, b, routes);
    scan_kernel<<<1, 256>>>(routes, inv);
    gather_kernel<<<N_TOK, 256>>>(
        (const float4*)x, inv, (float4*)out);
}

// round 9
// speedup vs baseline: 1.4214x; 1.4214x over previous
#include <cuda_runtime.h>
#include <cuda_bf16.h>
#include <cstdint>

// Problem constants (fixed by the reference)
#define N_TOK 16384      // B*S = 8*2048
#define D_DIM 4096
#define D_VEC 1024       // D/4 float4 per row
#define N_EXP 8
#define CAP   2048       // capacity = B*S/E
#define WL_MAX 4096      // marginal-token worklist capacity

// Scratch (no device allocs allowed) ---------------------------------------
__device__ int g_routes[N_TOK];
__device__ int g_inv[N_TOK];     // inv[e*CAP + p] = source token (valid iff p < g_cnt[e])
__device__ int g_cnt[N_EXP];     // per-expert total routed count
__device__ int g_wl[WL_MAX];     // tokens with top-2 margin < threshold
__device__ int g_wl_cnt;

// packed dual-FMA: d.lo += a.lo*b.lo ; d.hi += a.hi*b.hi
__device__ __forceinline__ void fma2(unsigned long long& d,
                                     unsigned long long a,
                                     unsigned long long b) {
    asm("fma.rn.f32x2 %0, %1, %2, %0;" : "+l"(d) : "l"(a), "l"(b));
}
__device__ __forceinline__ float unpack_sum(unsigned long long v) {
    float2 f = *reinterpret_cast<float2*>(&v);
    return f.x + f.y;
}

// ---------------------------------------------------------------------------
// Pass 0: reset worklist counter
// ---------------------------------------------------------------------------
__global__ void zero_kernel() { g_wl_cnt = 0; }

// ---------------------------------------------------------------------------
// Pass 1: routing (exact fp32 via packed f32x2 FMA; halves FFMA issue).
// Each warp computes logits for 4 tokens; W (128KB) is L1/L2-resident and
// shared across the CTA; x streams once from HBM. Marginal tokens go to the
// fp64 refinement worklist.
// ---------------------------------------------------------------------------
__global__ void __launch_bounds__(256) route_kernel(
    const ulonglong2* __restrict__ x,   // [N_TOK][512] 16B packs
    const ulonglong2* __restrict__ W,   // [8][512]
    const float*      __restrict__ b,   // [8]
    int* __restrict__ routes)
{
    const int warp = threadIdx.x >> 5;
    const int lane = threadIdx.x & 31;
    const int tbase = (blockIdx.x * 8 + warp) * 4;   // first of 4 tokens

    const ulonglong2* x0 = x + (size_t)tbase * D_VEC;

    unsigned long long acc[4][N_EXP];
#pragma unroll
    for (int t = 0; t < 4; t++)
#pragma unroll
        for (int e = 0; e < N_EXP; e++) acc[t][e] = 0ull;

#pragma unroll 4
    for (int i = 0; i < 32; i++) {
        const int idx = i * 32 + lane;
        ulonglong2 xv0 = __ldg(x0 + idx);
        ulonglong2 xv1 = __ldg(x0 + D_VEC + idx);
        ulonglong2 xv2 = __ldg(x0 + 2 * D_VEC + idx);
        ulonglong2 xv3 = __ldg(x0 + 3 * D_VEC + idx);
#pragma unroll
        for (int e = 0; e < N_EXP; e++) {
            ulonglong2 wv = __ldg(W + e * D_VEC + idx);
            fma2(acc[0][e], xv0.x, wv.x); fma2(acc[0][e], xv0.y, wv.y);
            fma2(acc[1][e], xv1.x, wv.x); fma2(acc[1][e], xv1.y, wv.y);
            fma2(acc[2][e], xv2.x, wv.x); fma2(acc[2][e], xv2.y, wv.y);
            fma2(acc[3][e], xv3.x, wv.x); fma2(acc[3][e], xv3.y, wv.y);
        }
    }

    // collapse packed halves, butterfly reduce across the warp
    float red[4][N_EXP];
#pragma unroll
    for (int t = 0; t < 4; t++) {
#pragma unroll
        for (int e = 0; e < N_EXP; e++) {
            float v = unpack_sum(acc[t][e]);
#pragma unroll
            for (int off = 16; off > 0; off >>= 1)
                v += __shfl_xor_sync(0xFFFFFFFFu, v, off);
            red[t][e] = v;
        }
    }

    if (lane == 0) {
#pragma unroll
        for (int t = 0; t < 4; t++) {
            float best = -1e30f, second = -1e30f;
            int bi = 0;
#pragma unroll
            for (int e = 0; e < N_EXP; e++) {
                float l = red[t][e] + b[e];
                if (l > best) { second = best; best = l; bi = e; }
                else if (l > second) { second = l; }
            }
            routes[tbase + t] = bi;
            if (best - second < 1e-3f) {   // marginal: exact fp64 re-rank later
                int slot = atomicAdd(&g_wl_cnt, 1);
                if (slot < WL_MAX) g_wl[slot] = tbase + t;
            }
        }
    }
}

// ---------------------------------------------------------------------------
// Pass 1b: fp64 refinement of marginal tokens (expected ~10 tokens).
// ---------------------------------------------------------------------------
__global__ void __launch_bounds__(256) refine_kernel(
    const float* __restrict__ x,
    const float* __restrict__ W,
    const float* __restrict__ b,
    int* __restrict__ routes)
{
    __shared__ double sred[8][N_EXP];
    const int tid  = threadIdx.x;
    const int warp = tid >> 5;
    const int lane = tid & 31;

    int cnt = g_wl_cnt;
    if (cnt > WL_MAX) cnt = WL_MAX;

    for (int w = blockIdx.x; w < cnt; w += gridDim.x) {
        const int tok = g_wl[w];
        const float* xr = x + (size_t)tok * D_DIM;

        double p[N_EXP];
#pragma unroll
        for (int e = 0; e < N_EXP; e++) p[e] = 0.0;

        for (int d = tid; d < D_DIM; d += 256) {
            const double xv = (double)__ldg(xr + d);
#pragma unroll
            for (int e = 0; e < N_EXP; e++)
                p[e] += xv * (double)__ldg(W + e * D_DIM + d);
        }

#pragma unroll
        for (int e = 0; e < N_EXP; e++) {
            double v = p[e];
#pragma unroll
            for (int off = 16; off > 0; off >>= 1)
                v += __shfl_xor_sync(0xFFFFFFFFu, v, off);
            if (lane == 0) sred[warp][e] = v;
        }
        __syncthreads();

        if (tid == 0) {
            double best = -1e300; int bi = 0;
#pragma unroll
            for (int e = 0; e < N_EXP; e++) {
                double s = (double)b[e];
#pragma unroll
                for (int wi = 0; wi < 8; wi++) s += sred[wi][e];
                if (s > best) { best = s; bi = e; }   // strict > : first-max
            }
            routes[tok] = bi;
        }
        __syncthreads();
    }
}

// ---------------------------------------------------------------------------
// Pass 2: stable positions. 1024 threads, 16 tokens each (int4 loads).
// Per-thread expert counts -> warp-parallel exclusive scan (8 warps, one
// expert column each) -> fill inv for kept tokens. No inv init needed:
// validity in gather is p < g_cnt[e].
// ---------------------------------------------------------------------------
__global__ void __launch_bounds__(1024) scan_kernel(
    const int4* __restrict__ routes4, int* __restrict__ inv)
{
    __shared__ int cnt[1024][N_EXP + 1];   // pad 9 -> conflict-free column reads
    const int t    = threadIdx.x;
    const int warp = t >> 5;
    const int lane = t & 31;

    // load this thread's 16 routes into registers
    int toks[16];
    const int4* rp = routes4 + t * 4;
#pragma unroll
    for (int q = 0; q < 4; q++) {
        int4 v = __ldg(rp + q);
        toks[q * 4 + 0] = v.x; toks[q * 4 + 1] = v.y;
        toks[q * 4 + 2] = v.z; toks[q * 4 + 3] = v.w;
    }

    int c[N_EXP];
#pragma unroll
    for (int e = 0; e < N_EXP; e++) c[e] = 0;
#pragma unroll
    for (int k = 0; k < 16; k++) c[toks[k]]++;
#pragma unroll
    for (int e = 0; e < N_EXP; e++) cnt[t][e] = c[e];
    __syncthreads();

    // warps 0..7: exclusive scan of expert column e over 1024 entries
    if (warp < N_EXP) {
        const int e = warp;
        int carry = 0;
        for (int j = 0; j < 32; j++) {
            const int idx = j * 32 + lane;
            int v = cnt[idx][e];
            int s = v;
#pragma unroll
            for (int o = 1; o < 32; o <<= 1) {
                int n = __shfl_up_sync(0xFFFFFFFFu, s, o);
                if (lane >= o) s += n;
            }
            cnt[idx][e] = s - v + carry;               // exclusive + carry
            carry += __shfl_sync(0xFFFFFFFFu, s, 31);  // chunk total
        }
        if (lane == 0) g_cnt[e] = carry;
    }
    __syncthreads();

    int off[N_EXP];
#pragma unroll
    for (int e = 0; e < N_EXP; e++) off[e] = cnt[t][e];

    const int base = t * 16;
#pragma unroll
    for (int k = 0; k < 16; k++) {
        const int r = toks[k];
        const int p = off[r]++;
        if (p < CAP) inv[r * CAP + p] = base + k;
    }
}

// ---------------------------------------------------------------------------
// Pass 3: gather. One CTA per output row: copy x[inv[row]] or write zeros.
// ---------------------------------------------------------------------------
__global__ void __launch_bounds__(256) gather_kernel(
    const float4* __restrict__ x,
    const int*   __restrict__ inv,
    float4* __restrict__ out)
{
    const int row = blockIdx.x;
    const int e = row >> 11;          // row / CAP
    const int p = row & (CAP - 1);
    float4* o = out + (size_t)row * D_VEC;
    const int t = threadIdx.x;

    if (p < g_cnt[e]) {
        const int src = __ldg(inv + row);      // uniform broadcast
        const float4* s = x + (size_t)src * D_VEC;
#pragma unroll
        for (int i = 0; i < 4; i++)
            o[t + 256 * i] = __ldg(s + t + 256 * i);
    } else {
        const float4 z = make_float4(0.f, 0.f, 0.f, 0.f);
#pragma unroll
        for (int i = 0; i < 4; i++)
            o[t + 256 * i] = z;
    }
}

// ---------------------------------------------------------------------------
extern "C" void kernel_launch(void* const* d_in, const int* in_sizes, int n_in,
                              void* d_out, int out_size)
{
    const float* x = (const float*)d_in[0];   // [8,2048,4096]
    const float* W = (const float*)d_in[1];   // [8,4096]
    const float* b = (const float*)d_in[2];   // [8]
    float* out = (float*)d_out;               // [16384,4096]

    int* routes; cudaGetSymbolAddress((void**)&routes, g_routes);
    int* inv;    cudaGetSymbolAddress((void**)&inv,    g_inv);

    zero_kernel<<<1, 1>>>();
    route_kernel<<<N_TOK / 32, 256>>>(
        (const ulonglong2*)x, (const ulonglong2*)W, b, routes);
    refine_kernel<<<64, 256>>>(x, W, b, routes);
    scan_kernel<<<1, 1024>>>((const int4*)routes, inv);
    gather_kernel<<<N_TOK, 256>>>(
        (const float4*)x, inv, (float4*)out);
}

// round 10
// speedup vs baseline: 1.4739x; 1.0369x over previous
#include <cuda_runtime.h>
#include <cuda_bf16.h>
#include <cstdint>

// Problem constants (fixed by the reference)
#define N_TOK 16384      // B*S = 8*2048
#define D_DIM 4096
#define D_VEC 1024       // D/4 16-byte packs per row
#define N_EXP 8
#define CAP   2048       // capacity = B*S/E
#define MARGIN_TH 1e-3f  // fp64 re-rank threshold (noise ~1e-6 both sides)

// Scratch (no device allocs allowed) ---------------------------------------
__device__ int   g_routes[N_TOK];
__device__ int   g_inv[N_TOK];    // inv[e*CAP+p] = source token (valid iff p < g_cnt[e])
__device__ int   g_cnt[N_EXP];    // per-expert routed totals
__device__ float g_margin[N_TOK]; // top-2 logit margin per token

// packed dual-FMA: d.lo += a.lo*b.lo ; d.hi += a.hi*b.hi
__device__ __forceinline__ void fma2(unsigned long long& d,
                                     unsigned long long a,
                                     unsigned long long b) {
    asm("fma.rn.f32x2 %0, %1, %2, %0;" : "+l"(d) : "l"(a), "l"(b));
}
__device__ __forceinline__ float unpack_sum(unsigned long long v) {
    float2 f = *reinterpret_cast<float2*>(&v);
    return f.x + f.y;
}

// ---------------------------------------------------------------------------
// Pass 1: routing. W staged once per CTA into 128KB smem (kills the 512MB
// L2 W-re-read that dominated R9's route). 512 threads = 16 warps x 4 tokens
// = 64 tokens/CTA -> 256 CTAs. x streams once from HBM; packed f32x2 FMA.
// ---------------------------------------------------------------------------
extern __shared__ ulonglong2 sW[];   // [8][1024] 16B packs = 128KB

__global__ void __launch_bounds__(512, 1) route_kernel(
    const ulonglong2* __restrict__ x,   // [N_TOK][1024]
    const ulonglong2* __restrict__ W,   // [8][1024]
    const float*      __restrict__ b,   // [8]
    int*   __restrict__ routes,
    float* __restrict__ margin)
{
    // stage W: 8192 16B packs, 512 threads -> 16 coalesced loads each
    for (int i = threadIdx.x; i < N_EXP * D_VEC; i += 512)
        sW[i] = __ldg(W + i);
    __syncthreads();

    const int warp = threadIdx.x >> 5;
    const int lane = threadIdx.x & 31;
    const int tbase = (blockIdx.x * 16 + warp) * 4;   // first of 4 tokens

    const ulonglong2* x0 = x + (size_t)tbase * D_VEC;

    unsigned long long acc[4][N_EXP];
#pragma unroll
    for (int t = 0; t < 4; t++)
#pragma unroll
        for (int e = 0; e < N_EXP; e++) acc[t][e] = 0ull;

#pragma unroll 2
    for (int i = 0; i < 32; i++) {
        const int idx = i * 32 + lane;
        ulonglong2 xv0 = __ldg(x0 + idx);
        ulonglong2 xv1 = __ldg(x0 + D_VEC + idx);
        ulonglong2 xv2 = __ldg(x0 + 2 * D_VEC + idx);
        ulonglong2 xv3 = __ldg(x0 + 3 * D_VEC + idx);
#pragma unroll
        for (int e = 0; e < N_EXP; e++) {
            ulonglong2 wv = sW[e * D_VEC + idx];
            fma2(acc[0][e], xv0.x, wv.x); fma2(acc[0][e], xv0.y, wv.y);
            fma2(acc[1][e], xv1.x, wv.x); fma2(acc[1][e], xv1.y, wv.y);
            fma2(acc[2][e], xv2.x, wv.x); fma2(acc[2][e], xv2.y, wv.y);
            fma2(acc[3][e], xv3.x, wv.x); fma2(acc[3][e], xv3.y, wv.y);
        }
    }

    // collapse packed halves, butterfly reduce across the warp
    float red[4][N_EXP];
#pragma unroll
    for (int t = 0; t < 4; t++) {
#pragma unroll
        for (int e = 0; e < N_EXP; e++) {
            float v = unpack_sum(acc[t][e]);
#pragma unroll
            for (int off = 16; off > 0; off >>= 1)
                v += __shfl_xor_sync(0xFFFFFFFFu, v, off);
            red[t][e] = v;
        }
    }

    if (lane == 0) {
#pragma unroll
        for (int t = 0; t < 4; t++) {
            float best = -1e30f, second = -1e30f;
            int bi = 0;
#pragma unroll
            for (int e = 0; e < N_EXP; e++) {
                float l = red[t][e] + b[e];
                if (l > best) { second = best; best = l; bi = e; }
                else if (l > second) { second = l; }
            }
            routes[tbase + t] = bi;
            margin[tbase + t] = best - second;
        }
    }
}

// ---------------------------------------------------------------------------
// Pass 1b: fp64 refinement. 64 blocks x 256 tokens each: parallel margin
// check -> local smem list -> exact fp64 8-way dot per marginal token
// (expected ~10 chip-wide). Removes all my-side argmax noise.
// ---------------------------------------------------------------------------
__global__ void __launch_bounds__(256) refine_kernel(
    const float* __restrict__ x,
    const float* __restrict__ W,
    const float* __restrict__ b,
    int* __restrict__ routes)
{
    __shared__ int    list[256];
    __shared__ int    nlist;
    __shared__ double sred[8][N_EXP];

    const int tid  = threadIdx.x;
    const int warp = tid >> 5;
    const int lane = tid & 31;
    const int tok0 = blockIdx.x * 256;

    if (tid == 0) nlist = 0;
    __syncthreads();

    if (g_margin[tok0 + tid] < MARGIN_TH) {
        int s = atomicAdd(&nlist, 1);
        list[s] = tok0 + tid;
    }
    __syncthreads();

    const int n = nlist;
    for (int w = 0; w < n; w++) {
        const int tok = list[w];
        const float* xr = x + (size_t)tok * D_DIM;

        double p[N_EXP];
#pragma unroll
        for (int e = 0; e < N_EXP; e++) p[e] = 0.0;

        for (int d = tid; d < D_DIM; d += 256) {
            const double xv = (double)__ldg(xr + d);
#pragma unroll
            for (int e = 0; e < N_EXP; e++)
                p[e] += xv * (double)__ldg(W + e * D_DIM + d);
        }

#pragma unroll
        for (int e = 0; e < N_EXP; e++) {
            double v = p[e];
#pragma unroll
            for (int off = 16; off > 0; off >>= 1)
                v += __shfl_xor_sync(0xFFFFFFFFu, v, off);
            if (lane == 0) sred[warp][e] = v;
        }
        __syncthreads();

        if (tid == 0) {
            double best = -1e300; int bi = 0;
#pragma unroll
            for (int e = 0; e < N_EXP; e++) {
                double s = (double)b[e];
#pragma unroll
                for (int wi = 0; wi < 8; wi++) s += sred[wi][e];
                if (s > best) { best = s; bi = e; }   // strict > : first-max
            }
            routes[tok] = bi;
        }
        __syncthreads();
    }
}

// ---------------------------------------------------------------------------
// Pass 2: stable positions, fully register/shfl-based (no local-mem spills,
// no serial column scan). 1024 threads x 16 tokens. Per-thread histogram in
// one u64 (8x8-bit), offsets in two u64s (4x16-bit each). Three-level scan:
// warp shfl-scan -> warp0 scans 32 warp totals -> add bases.
// ---------------------------------------------------------------------------
__global__ void __launch_bounds__(1024) scan_kernel(
    const int4* __restrict__ routes4, int* __restrict__ inv)
{
    __shared__ unsigned long long wtot_lo[32], wtot_hi[32];
    __shared__ unsigned long long base_lo[32], base_hi[32];

    const int t    = threadIdx.x;
    const int warp = t >> 5;
    const int lane = t & 31;

    // this thread's 16 routes
    int toks[16];
    const int4* rp = routes4 + t * 4;
#pragma unroll
    for (int q = 0; q < 4; q++) {
        int4 v = __ldg(rp + q);
        toks[q * 4 + 0] = v.x; toks[q * 4 + 1] = v.y;
        toks[q * 4 + 2] = v.z; toks[q * 4 + 3] = v.w;
    }

    // packed histogram: 8 experts x 8 bits (counts <= 16)
    unsigned long long h = 0ull;
#pragma unroll
    for (int k = 0; k < 16; k++) h += 1ull << (toks[k] * 8);

    // spread to 16-bit fields: lo = experts 0..3, hi = experts 4..7
    unsigned long long g = h >> 32;
    unsigned long long lo =  (h & 0xFFull)        | ((h & 0xFF00ull) << 8)
                          | ((h & 0xFF0000ull) << 16) | ((h & 0xFF000000ull) << 24);
    unsigned long long hi =  (g & 0xFFull)        | ((g & 0xFF00ull) << 8)
                          | ((g & 0xFF0000ull) << 16) | ((g & 0xFF000000ull) << 24);

    // level 1: inclusive warp scan of packed fields
    unsigned long long slo = lo, shi = hi;
#pragma unroll
    for (int o = 1; o < 32; o <<= 1) {
        unsigned long long nl = __shfl_up_sync(0xFFFFFFFFu, slo, o);
        unsigned long long nh = __shfl_up_sync(0xFFFFFFFFu, shi, o);
        if (lane >= o) { slo += nl; shi += nh; }
    }
    const unsigned long long elo = slo - lo;   // exclusive within warp
    const unsigned long long ehi = shi - hi;
    if (lane == 31) { wtot_lo[warp] = slo; wtot_hi[warp] = shi; }
    __syncthreads();

    // level 2: warp 0 scans the 32 warp totals (fields <= 16384, fit 16 bits)
    if (warp == 0) {
        unsigned long long tlo = wtot_lo[lane], thi = wtot_hi[lane];
        unsigned long long plo = tlo, phi = thi;
#pragma unroll
        for (int o = 1; o < 32; o <<= 1) {
            unsigned long long nl = __shfl_up_sync(0xFFFFFFFFu, plo, o);
            unsigned long long nh = __shfl_up_sync(0xFFFFFFFFu, phi, o);
            if (lane >= o) { plo += nl; phi += nh; }
        }
        base_lo[lane] = plo - tlo;
        base_hi[lane] = phi - thi;
        if (lane == 31) {
#pragma unroll
            for (int e = 0; e < 4; e++) {
                g_cnt[e]     = (int)((plo >> (e * 16)) & 0xFFFF);
                g_cnt[e + 4] = (int)((phi >> (e * 16)) & 0xFFFF);
            }
        }
    }
    __syncthreads();

    // level 3: per-thread running offsets, packed; fill inverse map
    unsigned long long mylo = elo + base_lo[warp];
    unsigned long long myhi = ehi + base_hi[warp];
    const int base = t * 16;
#pragma unroll
    for (int k = 0; k < 16; k++) {
        const int r = toks[k];
        const int sh = (r & 3) * 16;
        const bool low = r < 4;
        const int p = (int)(((low ? mylo : myhi) >> sh) & 0xFFFF);
        const unsigned long long inc = 1ull << sh;
        if (low) mylo += inc; else myhi += inc;
        if (p < CAP) inv[r * CAP + p] = base + k;
    }
}

// ---------------------------------------------------------------------------
// Pass 3: gather. One CTA per output row: copy x[inv[row]] or write zeros.
// ---------------------------------------------------------------------------
__global__ void __launch_bounds__(256) gather_kernel(
    const float4* __restrict__ x,
    const int*   __restrict__ inv,
    float4* __restrict__ out)
{
    const int row = blockIdx.x;
    const int e = row >> 11;          // row / CAP
    const int p = row & (CAP - 1);
    float4* o = out + (size_t)row * D_VEC;
    const int t = threadIdx.x;

    if (p < g_cnt[e]) {
        const int src = __ldg(inv + row);      // uniform broadcast
        const float4* s = x + (size_t)src * D_VEC;
#pragma unroll
        for (int i = 0; i < 4; i++)
            o[t + 256 * i] = __ldg(s + t + 256 * i);
    } else {
        const float4 z = make_float4(0.f, 0.f, 0.f, 0.f);
#pragma unroll
        for (int i = 0; i < 4; i++)
            o[t + 256 * i] = z;
    }
}

// ---------------------------------------------------------------------------
extern "C" void kernel_launch(void* const* d_in, const int* in_sizes, int n_in,
                              void* d_out, int out_size)
{
    const float* x = (const float*)d_in[0];   // [8,2048,4096]
    const float* W = (const float*)d_in[1];   // [8,4096]
    const float* b = (const float*)d_in[2];   // [8]
    float* out = (float*)d_out;               // [16384,4096]

    int* routes;   cudaGetSymbolAddress((void**)&routes, g_routes);
    int* inv;      cudaGetSymbolAddress((void**)&inv,    g_inv);
    float* margin; cudaGetSymbolAddress((void**)&margin, g_margin);

    static bool attr_done = false;
    if (!attr_done) {
        cudaFuncSetAttribute(route_kernel,
                             cudaFuncAttributeMaxDynamicSharedMemorySize,
                             N_EXP * D_VEC * 16);   // 128KB
        attr_done = true;
    }

    route_kernel<<<N_TOK / 64, 512, N_EXP * D_VEC * 16>>>(
        (const ulonglong2*)x, (const ulonglong2*)W, b, routes, margin);
    refine_kernel<<<64, 256>>>(x, W, b, routes);
    scan_kernel<<<1, 1024>>>((const int4*)routes, inv);
    gather_kernel<<<N_TOK, 256>>>(
        (const float4*)x, inv, (float4*)out);
}